// round 1
// baseline (speedup 1.0000x reference)
#include <cuda_runtime.h>
#include <math.h>

// Problem constants (fixed by the reference).
#define NB   4
#define SEQ  2048
#define DIM  1024

// Scratch (allocations are forbidden; __device__ globals are the sanctioned path).
__device__ float g_q[(size_t)NB * SEQ * DIM];          // 32 MB
__device__ float g_k[(size_t)NB * SEQ * DIM];          // 32 MB
__device__ float g_v[(size_t)NB * SEQ * DIM];          // 32 MB
__device__ float g_p[(size_t)NB * SEQ * SEQ];          // 64 MB (scores/probs)

// ---------------------------------------------------------------------------
// Projection GEMM:  Y[m,e] = sum_d X[m,d] * W[e,d]   (C = A * B^T, both K-major)
// M = NB*SEQ = 8192, E = DIM = 1024, K = DIM = 1024.
// 64x64 tile, BK=16, 256 threads, 4x4 register micro-tile.
// ---------------------------------------------------------------------------
__global__ void __launch_bounds__(256) proj_kernel(const float* __restrict__ X,
                                                   const float* __restrict__ W,
                                                   float* __restrict__ Y)
{
    __shared__ __align__(16) float As[16][68];
    __shared__ __align__(16) float Bs[16][68];

    const int m0 = blockIdx.y * 64;
    const int e0 = blockIdx.x * 64;
    const int tid = threadIdx.x;
    const int tx = tid & 15;
    const int ty = tid >> 4;

    const float* a = X + (size_t)m0 * DIM;
    const float* b = W + (size_t)e0 * DIM;

    float acc[4][4] = {};

    for (int k0 = 0; k0 < DIM; k0 += 16) {
        #pragma unroll
        for (int i = 0; i < 4; i++) {
            int idx = tid + i * 256;
            int r = idx >> 4;
            int c = idx & 15;
            As[c][r] = a[(size_t)r * DIM + k0 + c];
            Bs[c][r] = b[(size_t)r * DIM + k0 + c];
        }
        __syncthreads();
        #pragma unroll
        for (int k = 0; k < 16; k++) {
            float4 av = *(const float4*)&As[k][ty * 4];
            float4 bv = *(const float4*)&Bs[k][tx * 4];
            float ar[4] = {av.x, av.y, av.z, av.w};
            float br[4] = {bv.x, bv.y, bv.z, bv.w};
            #pragma unroll
            for (int i = 0; i < 4; i++)
                #pragma unroll
                for (int j = 0; j < 4; j++)
                    acc[i][j] += ar[i] * br[j];
        }
        __syncthreads();
    }

    #pragma unroll
    for (int i = 0; i < 4; i++) {
        float4 v = make_float4(acc[i][0], acc[i][1], acc[i][2], acc[i][3]);
        *(float4*)&Y[(size_t)(m0 + ty * 4 + i) * DIM + e0 + tx * 4] = v;
    }
}

// ---------------------------------------------------------------------------
// Scores:  P[n,s,t] = (q . k) / sqrt(D), with t>s -> -inf.  Only lower-triangle
// 64x64 tiles are computed; upper tiles are never touched (and never read).
// ---------------------------------------------------------------------------
__global__ void __launch_bounds__(256) scores_kernel()
{
    const int bj = blockIdx.x;   // key tile
    const int bi = blockIdx.y;   // query tile
    const int n  = blockIdx.z;
    if (bj > bi) return;

    __shared__ __align__(16) float As[16][68];
    __shared__ __align__(16) float Bs[16][68];

    const int tid = threadIdx.x;
    const int tx = tid & 15;
    const int ty = tid >> 4;
    const int s0 = bi * 64;
    const int t0 = bj * 64;

    const float* q  = g_q + ((size_t)n * SEQ + s0) * DIM;
    const float* kk = g_k + ((size_t)n * SEQ + t0) * DIM;

    float acc[4][4] = {};

    for (int k0 = 0; k0 < DIM; k0 += 16) {
        #pragma unroll
        for (int i = 0; i < 4; i++) {
            int idx = tid + i * 256;
            int r = idx >> 4;
            int c = idx & 15;
            As[c][r] = q [(size_t)r * DIM + k0 + c];
            Bs[c][r] = kk[(size_t)r * DIM + k0 + c];
        }
        __syncthreads();
        #pragma unroll
        for (int k = 0; k < 16; k++) {
            float4 av = *(const float4*)&As[k][ty * 4];
            float4 bv = *(const float4*)&Bs[k][tx * 4];
            float ar[4] = {av.x, av.y, av.z, av.w};
            float br[4] = {bv.x, bv.y, bv.z, bv.w};
            #pragma unroll
            for (int i = 0; i < 4; i++)
                #pragma unroll
                for (int j = 0; j < 4; j++)
                    acc[i][j] += ar[i] * br[j];
        }
        __syncthreads();
    }

    const float scale = 0.03125f;  // 1/sqrt(1024)
    #pragma unroll
    for (int i = 0; i < 4; i++) {
        int sg = s0 + ty * 4 + i;
        float vals[4];
        #pragma unroll
        for (int j = 0; j < 4; j++) {
            int tg = t0 + tx * 4 + j;
            float v = acc[i][j] * scale;
            vals[j] = (tg > sg) ? -INFINITY : v;
        }
        *(float4*)&g_p[((size_t)n * SEQ + sg) * SEQ + t0 + tx * 4] =
            make_float4(vals[0], vals[1], vals[2], vals[3]);
    }
}

// ---------------------------------------------------------------------------
// Row softmax over the causal prefix [0, s]; zero-fill (s, tile_end) so the
// PV GEMM can consume full 16-wide K-tiles up to the diagonal tile boundary.
// ---------------------------------------------------------------------------
__global__ void __launch_bounds__(256) softmax_kernel()
{
    const int s = blockIdx.x;
    const int n = blockIdx.y;
    float* row = g_p + ((size_t)n * SEQ + s) * SEQ;
    const int len = s + 1;
    const int tile_end = ((s >> 6) + 1) << 6;
    const int tid = threadIdx.x;

    __shared__ float red[8];

    float m = -INFINITY;
    for (int t = tid; t < len; t += 256) m = fmaxf(m, row[t]);
    #pragma unroll
    for (int o = 16; o > 0; o >>= 1) m = fmaxf(m, __shfl_xor_sync(0xffffffffu, m, o));
    if ((tid & 31) == 0) red[tid >> 5] = m;
    __syncthreads();
    float bm = -INFINITY;
    #pragma unroll
    for (int w = 0; w < 8; w++) bm = fmaxf(bm, red[w]);
    __syncthreads();

    float ssum = 0.f;
    for (int t = tid; t < len; t += 256) {
        float e = __expf(row[t] - bm);
        row[t] = e;
        ssum += e;
    }
    #pragma unroll
    for (int o = 16; o > 0; o >>= 1) ssum += __shfl_xor_sync(0xffffffffu, ssum, o);
    if ((tid & 31) == 0) red[tid >> 5] = ssum;
    __syncthreads();
    float tot = 0.f;
    #pragma unroll
    for (int w = 0; w < 8; w++) tot += red[w];

    const float inv = 1.0f / tot;
    for (int t = tid; t < len; t += 256) row[t] *= inv;
    for (int t = len + tid; t < tile_end; t += 256) row[t] = 0.f;
}

// ---------------------------------------------------------------------------
// PV:  Y[n,s,e] = sum_{t<=s} P[s,t] * V[t,e].  A is K-major (P row-major),
// B is row-major [K,E] (plain NN load).  K-loop stops at the diagonal tile.
// ---------------------------------------------------------------------------
__global__ void __launch_bounds__(256) pv_kernel(float* __restrict__ Y)
{
    const int e0 = blockIdx.x * 64;
    const int bi = blockIdx.y;     // s tile
    const int n  = blockIdx.z;
    const int s0 = bi * 64;

    __shared__ __align__(16) float As[16][68];
    __shared__ __align__(16) float Bs[16][68];

    const int tid = threadIdx.x;
    const int tx = tid & 15;
    const int ty = tid >> 4;

    const float* P = g_p + ((size_t)n * SEQ + s0) * SEQ;
    const float* V = g_v + (size_t)n * SEQ * DIM;

    float acc[4][4] = {};

    const int ktiles = (bi + 1) * 4;  // (s0+64)/16
    for (int kt = 0; kt < ktiles; kt++) {
        const int t0 = kt * 16;
        #pragma unroll
        for (int i = 0; i < 4; i++) {
            int idx = tid + i * 256;
            int rA = idx >> 4;
            int cA = idx & 15;
            As[cA][rA] = P[(size_t)rA * SEQ + t0 + cA];
            int kB = idx >> 6;
            int nn = idx & 63;
            Bs[kB][nn] = V[(size_t)(t0 + kB) * DIM + e0 + nn];
        }
        __syncthreads();
        #pragma unroll
        for (int k = 0; k < 16; k++) {
            float4 av = *(const float4*)&As[k][ty * 4];
            float4 bv = *(const float4*)&Bs[k][tx * 4];
            float ar[4] = {av.x, av.y, av.z, av.w};
            float br[4] = {bv.x, bv.y, bv.z, bv.w};
            #pragma unroll
            for (int i = 0; i < 4; i++)
                #pragma unroll
                for (int j = 0; j < 4; j++)
                    acc[i][j] += ar[i] * br[j];
        }
        __syncthreads();
    }

    #pragma unroll
    for (int i = 0; i < 4; i++) {
        float4 v = make_float4(acc[i][0], acc[i][1], acc[i][2], acc[i][3]);
        *(float4*)&Y[((size_t)n * SEQ + s0 + ty * 4 + i) * DIM + e0 + tx * 4] = v;
    }
}

// ---------------------------------------------------------------------------
// Launch.  Inputs: [0]=query [1]=key [2]=value [3]=attn_mask (tril, implied by
// the causal condition, unused) [4]=Wq [5]=Wk [6]=Wv.  Output: [N,S,D] fp32.
// ---------------------------------------------------------------------------
extern "C" void kernel_launch(void* const* d_in, const int* in_sizes, int n_in,
                              void* d_out, int out_size)
{
    (void)in_sizes; (void)n_in; (void)out_size;
    const float* query = (const float*)d_in[0];
    const float* key   = (const float*)d_in[1];
    const float* value = (const float*)d_in[2];
    const float* Wq    = (const float*)d_in[4];
    const float* Wk    = (const float*)d_in[5];
    const float* Wv    = (const float*)d_in[6];
    float* out = (float*)d_out;

    float *q_ptr, *k_ptr, *v_ptr;
    cudaGetSymbolAddress((void**)&q_ptr, g_q);
    cudaGetSymbolAddress((void**)&k_ptr, g_k);
    cudaGetSymbolAddress((void**)&v_ptr, g_v);

    dim3 pg(DIM / 64, (NB * SEQ) / 64);          // 16 x 128
    proj_kernel<<<pg, 256>>>(query, Wq, q_ptr);
    proj_kernel<<<pg, 256>>>(key,   Wk, k_ptr);
    proj_kernel<<<pg, 256>>>(value, Wv, v_ptr);

    dim3 sg(SEQ / 64, SEQ / 64, NB);             // 32 x 32 x 4 (upper tiles no-op)
    scores_kernel<<<sg, 256>>>();

    dim3 smg(SEQ, NB);                           // one block per row
    softmax_kernel<<<smg, 256>>>();

    dim3 vg(DIM / 64, SEQ / 64, NB);             // 16 x 32 x 4
    pv_kernel<<<vg, 256>>>(out);
}

// round 2
// speedup vs baseline: 2.7383x; 2.7383x over previous
#include <cuda_runtime.h>
#include <math.h>

#define NB   4
#define SEQ  2048
#define DIM  1024

// Scratch (__device__ globals: allocations forbidden).
__device__ float g_q[(size_t)NB * SEQ * DIM];
__device__ float g_k[(size_t)NB * SEQ * DIM];
__device__ float g_v[(size_t)NB * SEQ * DIM];
__device__ float g_p[(size_t)NB * SEQ * SEQ];

// ---------------------------------------------------------------------------
// TF32 helpers
// ---------------------------------------------------------------------------
__device__ __forceinline__ unsigned f2tf(float f) {
    unsigned u;
    asm("cvt.rna.tf32.f32 %0, %1;" : "=r"(u) : "f"(f));
    return u;
}
__device__ __forceinline__ uint4 cvt4(float4 v) {
    return make_uint4(f2tf(v.x), f2tf(v.y), f2tf(v.z), f2tf(v.w));
}
__device__ __forceinline__ void mma8(float* c, const unsigned* a, const unsigned* b) {
    asm volatile(
        "mma.sync.aligned.m16n8k8.row.col.f32.tf32.tf32.f32 "
        "{%0,%1,%2,%3}, {%4,%5,%6,%7}, {%8,%9}, {%0,%1,%2,%3};"
        : "+f"(c[0]), "+f"(c[1]), "+f"(c[2]), "+f"(c[3])
        : "r"(a[0]), "r"(a[1]), "r"(a[2]), "r"(a[3]), "r"(b[0]), "r"(b[1]));
}

// ---------------------------------------------------------------------------
// C = A * B^T  (both A and B are K-major, K=1024).  128x128 tile, BK=16,
// 256 threads (8 warps, 2x4), 64x32 warp tile, tf32 mma m16n8k8.
// CAUSAL: skip upper 128-tiles, scale by 1/32, mask t>s with -inf.
// ---------------------------------------------------------------------------
template<bool CAUSAL>
__global__ void __launch_bounds__(256) gemm_tn(const float* __restrict__ Abase,
                                               const float* __restrict__ Bbase,
                                               float* __restrict__ Cbase,
                                               size_t sA, size_t sB, size_t sC,
                                               int ldc)
{
    const int bj = blockIdx.x, bi = blockIdx.y, n = blockIdx.z;
    if (CAUSAL && bj > bi) return;

    const float* A = Abase + (size_t)n * sA + (size_t)bi * 128 * DIM;
    const float* B = Bbase + (size_t)n * sB + (size_t)bj * 128 * DIM;
    float*       C = Cbase + (size_t)n * sC;
    const int m0 = bi * 128, e0 = bj * 128;

    __shared__ unsigned As[128][20];   // [row][k], pad 20 -> conflict-free frags
    __shared__ unsigned Bs[128][20];

    const int tid  = threadIdx.x;
    const int lane = tid & 31, warp = tid >> 5;
    const int wm = (warp >> 2) * 64, wn = (warp & 3) * 32;
    const int qr = lane >> 2, qc = lane & 3;

    const int ar = tid >> 2;          // 0..63 (second row = ar+64)
    const int ac = (tid & 3) * 4;     // 0,4,8,12

    float acc[4][4][4] = {};

    float4 pa0 = *(const float4*)&A[(size_t)ar * DIM + ac];
    float4 pa1 = *(const float4*)&A[(size_t)(ar + 64) * DIM + ac];
    float4 pb0 = *(const float4*)&B[(size_t)ar * DIM + ac];
    float4 pb1 = *(const float4*)&B[(size_t)(ar + 64) * DIM + ac];

    const int NK = DIM / 16;
    for (int kt = 0; kt < NK; kt++) {
        *(uint4*)&As[ar][ac]      = cvt4(pa0);
        *(uint4*)&As[ar + 64][ac] = cvt4(pa1);
        *(uint4*)&Bs[ar][ac]      = cvt4(pb0);
        *(uint4*)&Bs[ar + 64][ac] = cvt4(pb1);
        __syncthreads();

        if (kt + 1 < NK) {
            const int k0 = (kt + 1) * 16;
            pa0 = *(const float4*)&A[(size_t)ar * DIM + k0 + ac];
            pa1 = *(const float4*)&A[(size_t)(ar + 64) * DIM + k0 + ac];
            pb0 = *(const float4*)&B[(size_t)ar * DIM + k0 + ac];
            pb1 = *(const float4*)&B[(size_t)(ar + 64) * DIM + k0 + ac];
        }

        #pragma unroll
        for (int ks = 0; ks < 16; ks += 8) {
            unsigned af[4][4], bf[4][2];
            #pragma unroll
            for (int mi = 0; mi < 4; mi++) {
                const int r = wm + mi * 16 + qr;
                af[mi][0] = As[r][ks + qc];
                af[mi][1] = As[r + 8][ks + qc];
                af[mi][2] = As[r][ks + qc + 4];
                af[mi][3] = As[r + 8][ks + qc + 4];
            }
            #pragma unroll
            for (int ni = 0; ni < 4; ni++) {
                const int cc = wn + ni * 8 + qr;
                bf[ni][0] = Bs[cc][ks + qc];
                bf[ni][1] = Bs[cc][ks + qc + 4];
            }
            #pragma unroll
            for (int mi = 0; mi < 4; mi++)
                #pragma unroll
                for (int ni = 0; ni < 4; ni++)
                    mma8(acc[mi][ni], af[mi], bf[ni]);
        }
        __syncthreads();
    }

    #pragma unroll
    for (int mi = 0; mi < 4; mi++) {
        const int r0 = m0 + wm + mi * 16 + qr;
        #pragma unroll
        for (int ni = 0; ni < 4; ni++) {
            const int c = e0 + wn + ni * 8 + qc * 2;
            float v0 = acc[mi][ni][0], v1 = acc[mi][ni][1];
            float v2 = acc[mi][ni][2], v3 = acc[mi][ni][3];
            if (CAUSAL) {
                v0 *= 0.03125f; v1 *= 0.03125f; v2 *= 0.03125f; v3 *= 0.03125f;
                if (c     > r0)     v0 = -INFINITY;
                if (c + 1 > r0)     v1 = -INFINITY;
                if (c     > r0 + 8) v2 = -INFINITY;
                if (c + 1 > r0 + 8) v3 = -INFINITY;
            }
            *(float2*)&C[(size_t)r0 * ldc + c]       = make_float2(v0, v1);
            *(float2*)&C[(size_t)(r0 + 8) * ldc + c] = make_float2(v2, v3);
        }
    }
}

// ---------------------------------------------------------------------------
// Row softmax over causal prefix [0,s]; zero-fill up to 128-tile boundary so
// the PV GEMM consumes full K tiles.
// ---------------------------------------------------------------------------
__global__ void __launch_bounds__(256) softmax_kernel()
{
    const int s = blockIdx.x;
    const int n = blockIdx.y;
    float* row = g_p + ((size_t)n * SEQ + s) * SEQ;
    const int len = s + 1;
    const int tile_end = ((s >> 7) + 1) << 7;
    const int tid = threadIdx.x;

    __shared__ float red[8];

    float m = -INFINITY;
    for (int t = tid; t < len; t += 256) m = fmaxf(m, row[t]);
    #pragma unroll
    for (int o = 16; o > 0; o >>= 1) m = fmaxf(m, __shfl_xor_sync(0xffffffffu, m, o));
    if ((tid & 31) == 0) red[tid >> 5] = m;
    __syncthreads();
    float bm = -INFINITY;
    #pragma unroll
    for (int w = 0; w < 8; w++) bm = fmaxf(bm, red[w]);
    __syncthreads();

    float ssum = 0.f;
    for (int t = tid; t < len; t += 256) {
        float e = __expf(row[t] - bm);
        row[t] = e;
        ssum += e;
    }
    #pragma unroll
    for (int o = 16; o > 0; o >>= 1) ssum += __shfl_xor_sync(0xffffffffu, ssum, o);
    if ((tid & 31) == 0) red[tid >> 5] = ssum;
    __syncthreads();
    float tot = 0.f;
    #pragma unroll
    for (int w = 0; w < 8; w++) tot += red[w];

    const float inv = 1.0f / tot;
    for (int t = tid; t < len; t += 256) row[t] *= inv;
    for (int t = len + tid; t < tile_end; t += 256) row[t] = 0.f;
}

// ---------------------------------------------------------------------------
// Y = P * V  (NN GEMM).  A = P row-major [S,S], B = V row-major [S,D].
// As: [m][k] pad 20; Bs: [k][n] 16x136 (pad->136 is conflict-free for frags).
// K-loop truncated at the diagonal 128-tile.
// ---------------------------------------------------------------------------
__global__ void __launch_bounds__(256) pv_tf32(float* __restrict__ Y)
{
    const int bj = blockIdx.x;   // e tile
    const int bi = blockIdx.y;   // s tile
    const int n  = blockIdx.z;
    const int s0 = bi * 128, e0 = bj * 128;

    __shared__ unsigned As[128][20];
    __shared__ unsigned Bs[16][136];

    const float* P = g_p + (size_t)n * SEQ * SEQ + (size_t)s0 * SEQ;
    const float* V = g_v + (size_t)n * SEQ * DIM;

    const int tid  = threadIdx.x;
    const int lane = tid & 31, warp = tid >> 5;
    const int wm = (warp >> 2) * 64, wn = (warp & 3) * 32;
    const int qr = lane >> 2, qc = lane & 3;

    const int ar = tid >> 2,  ac = (tid & 3) * 4;     // A tile 128x16
    const int br = tid >> 5,  bc = (tid & 31) * 4;    // B tile 16x128 (rows br, br+8)

    float acc[4][4][4] = {};

    const int ktiles = (bi + 1) * 8;
    float4 pa0 = *(const float4*)&P[(size_t)ar * SEQ + ac];
    float4 pa1 = *(const float4*)&P[(size_t)(ar + 64) * SEQ + ac];
    float4 pb0 = *(const float4*)&V[(size_t)br * DIM + e0 + bc];
    float4 pb1 = *(const float4*)&V[(size_t)(br + 8) * DIM + e0 + bc];

    for (int kt = 0; kt < ktiles; kt++) {
        *(uint4*)&As[ar][ac]      = cvt4(pa0);
        *(uint4*)&As[ar + 64][ac] = cvt4(pa1);
        *(uint4*)&Bs[br][bc]      = cvt4(pb0);
        *(uint4*)&Bs[br + 8][bc]  = cvt4(pb1);
        __syncthreads();

        if (kt + 1 < ktiles) {
            const int t0 = (kt + 1) * 16;
            pa0 = *(const float4*)&P[(size_t)ar * SEQ + t0 + ac];
            pa1 = *(const float4*)&P[(size_t)(ar + 64) * SEQ + t0 + ac];
            pb0 = *(const float4*)&V[(size_t)(t0 + br) * DIM + e0 + bc];
            pb1 = *(const float4*)&V[(size_t)(t0 + br + 8) * DIM + e0 + bc];
        }

        #pragma unroll
        for (int ks = 0; ks < 16; ks += 8) {
            unsigned af[4][4], bf[4][2];
            #pragma unroll
            for (int mi = 0; mi < 4; mi++) {
                const int r = wm + mi * 16 + qr;
                af[mi][0] = As[r][ks + qc];
                af[mi][1] = As[r + 8][ks + qc];
                af[mi][2] = As[r][ks + qc + 4];
                af[mi][3] = As[r + 8][ks + qc + 4];
            }
            #pragma unroll
            for (int ni = 0; ni < 4; ni++) {
                const int cc = wn + ni * 8 + qr;
                bf[ni][0] = Bs[ks + qc][cc];
                bf[ni][1] = Bs[ks + qc + 4][cc];
            }
            #pragma unroll
            for (int mi = 0; mi < 4; mi++)
                #pragma unroll
                for (int ni = 0; ni < 4; ni++)
                    mma8(acc[mi][ni], af[mi], bf[ni]);
        }
        __syncthreads();
    }

    #pragma unroll
    for (int mi = 0; mi < 4; mi++) {
        const int r0 = s0 + wm + mi * 16 + qr;
        #pragma unroll
        for (int ni = 0; ni < 4; ni++) {
            const int c = e0 + wn + ni * 8 + qc * 2;
            *(float2*)&Y[((size_t)n * SEQ + r0) * DIM + c] =
                make_float2(acc[mi][ni][0], acc[mi][ni][1]);
            *(float2*)&Y[((size_t)n * SEQ + r0 + 8) * DIM + c] =
                make_float2(acc[mi][ni][2], acc[mi][ni][3]);
        }
    }
}

// ---------------------------------------------------------------------------
// Launch.
// ---------------------------------------------------------------------------
extern "C" void kernel_launch(void* const* d_in, const int* in_sizes, int n_in,
                              void* d_out, int out_size)
{
    (void)in_sizes; (void)n_in; (void)out_size;
    const float* query = (const float*)d_in[0];
    const float* key   = (const float*)d_in[1];
    const float* value = (const float*)d_in[2];
    const float* Wq    = (const float*)d_in[4];
    const float* Wk    = (const float*)d_in[5];
    const float* Wv    = (const float*)d_in[6];
    float* out = (float*)d_out;

    float *q_ptr, *k_ptr, *v_ptr, *p_ptr;
    cudaGetSymbolAddress((void**)&q_ptr, g_q);
    cudaGetSymbolAddress((void**)&k_ptr, g_k);
    cudaGetSymbolAddress((void**)&v_ptr, g_v);
    cudaGetSymbolAddress((void**)&p_ptr, g_p);

    // Projections: M=8192, N=1024, K=1024
    dim3 pg(DIM / 128, (NB * SEQ) / 128, 1);
    gemm_tn<false><<<pg, 256>>>(query, Wq, q_ptr, 0, 0, 0, DIM);
    gemm_tn<false><<<pg, 256>>>(key,   Wk, k_ptr, 0, 0, 0, DIM);
    gemm_tn<false><<<pg, 256>>>(value, Wv, v_ptr, 0, 0, 0, DIM);

    // Scores: causal, per batch
    dim3 sg(SEQ / 128, SEQ / 128, NB);
    gemm_tn<true><<<sg, 256>>>(q_ptr, k_ptr, p_ptr,
                               (size_t)SEQ * DIM, (size_t)SEQ * DIM,
                               (size_t)SEQ * SEQ, SEQ);

    dim3 smg(SEQ, NB);
    softmax_kernel<<<smg, 256>>>();

    dim3 vg(DIM / 128, SEQ / 128, NB);
    pv_tf32<<<vg, 256>>>(out);
}

// round 4
// speedup vs baseline: 2.8630x; 1.0456x over previous
#include <cuda_runtime.h>
#include <math.h>

#define NB   4
#define SEQ  2048
#define DIM  1024

__device__ float g_q[(size_t)NB * SEQ * DIM];
__device__ float g_k[(size_t)NB * SEQ * DIM];
__device__ float g_v[(size_t)NB * SEQ * DIM];
__device__ float g_p[(size_t)NB * SEQ * SEQ];

// ---------------------------------------------------------------------------
// Helpers
// ---------------------------------------------------------------------------
__device__ __forceinline__ unsigned f2tf(float f) {
    unsigned u;
    asm("cvt.rna.tf32.f32 %0, %1;" : "=r"(u) : "f"(f));
    return u;
}
__device__ __forceinline__ uint4 cvt4(float4 v) {
    return make_uint4(f2tf(v.x), f2tf(v.y), f2tf(v.z), f2tf(v.w));
}
__device__ __forceinline__ void mma8(float* c, const unsigned* a, const unsigned* b) {
    asm volatile(
        "mma.sync.aligned.m16n8k8.row.col.f32.tf32.tf32.f32 "
        "{%0,%1,%2,%3}, {%4,%5,%6,%7}, {%8,%9}, {%0,%1,%2,%3};"
        : "+f"(c[0]), "+f"(c[1]), "+f"(c[2]), "+f"(c[3])
        : "r"(a[0]), "r"(a[1]), "r"(a[2]), "r"(a[3]), "r"(b[0]), "r"(b[1]));
}
__device__ __forceinline__ unsigned su32(const void* p) {
    return (unsigned)__cvta_generic_to_shared(p);
}
__device__ __forceinline__ void ldsm4(unsigned* r, unsigned addr) {
    asm volatile("ldmatrix.sync.aligned.m8n8.x4.shared.b16 {%0,%1,%2,%3}, [%4];"
                 : "=r"(r[0]), "=r"(r[1]), "=r"(r[2]), "=r"(r[3]) : "r"(addr));
}

// ---------------------------------------------------------------------------
// C = A * B^T  (A, B K-major, K=1024).  128x128 tile, BK=16, 8 warps (2x4),
// 64x32 warp tile, tf32 mma, ldmatrix fragment loads.
// ---------------------------------------------------------------------------
template<bool CAUSAL>
__global__ void __launch_bounds__(256) gemm_tn(const float* __restrict__ Abase,
                                               const float* __restrict__ Bbase,
                                               float* __restrict__ Cbase,
                                               size_t sA, size_t sB, size_t sC,
                                               int ldc)
{
    const int bj = blockIdx.x, bi = blockIdx.y, n = blockIdx.z;
    if (CAUSAL && bj > bi) return;

    const float* A = Abase + (size_t)n * sA + (size_t)bi * 128 * DIM;
    const float* B = Bbase + (size_t)n * sB + (size_t)bj * 128 * DIM;
    float*       C = Cbase + (size_t)n * sC;
    const int m0 = bi * 128, e0 = bj * 128;

    __shared__ __align__(16) unsigned As[128][20];
    __shared__ __align__(16) unsigned Bs[128][20];

    const int tid  = threadIdx.x;
    const int lane = tid & 31, warp = tid >> 5;
    const int wm = (warp >> 2) * 64, wn = (warp & 3) * 32;
    const int qr = lane >> 2, qc = lane & 3;

    const int ar = tid >> 2;
    const int ac = (tid & 3) * 4;

    // ldmatrix per-lane row addresses
    const int aRow = wm + (lane & 7) + ((lane >> 3) & 1) * 8;
    const int aCol = (lane >> 4) * 4;
    const unsigned aAddr = su32(&As[aRow][aCol]);
    const int bRow = wn + (lane & 7) + (lane >> 4) * 8;
    const int bCol = ((lane >> 3) & 1) * 4;
    const unsigned bAddr = su32(&Bs[bRow][bCol]);

    float acc[4][4][4] = {};

    float4 pa0 = *(const float4*)&A[(size_t)ar * DIM + ac];
    float4 pa1 = *(const float4*)&A[(size_t)(ar + 64) * DIM + ac];
    float4 pb0 = *(const float4*)&B[(size_t)ar * DIM + ac];
    float4 pb1 = *(const float4*)&B[(size_t)(ar + 64) * DIM + ac];

    const int NK = DIM / 16;
    for (int kt = 0; kt < NK; kt++) {
        *(uint4*)&As[ar][ac]      = cvt4(pa0);
        *(uint4*)&As[ar + 64][ac] = cvt4(pa1);
        *(uint4*)&Bs[ar][ac]      = cvt4(pb0);
        *(uint4*)&Bs[ar + 64][ac] = cvt4(pb1);
        __syncthreads();

        if (kt + 1 < NK) {
            const int k0 = (kt + 1) * 16;
            pa0 = *(const float4*)&A[(size_t)ar * DIM + k0 + ac];
            pa1 = *(const float4*)&A[(size_t)(ar + 64) * DIM + k0 + ac];
            pb0 = *(const float4*)&B[(size_t)ar * DIM + k0 + ac];
            pb1 = *(const float4*)&B[(size_t)(ar + 64) * DIM + k0 + ac];
        }

        #pragma unroll
        for (int ks = 0; ks < 16; ks += 8) {
            unsigned af[4][4], bfr[2][4];
            #pragma unroll
            for (int mi = 0; mi < 4; mi++)
                ldsm4(af[mi], aAddr + (unsigned)(mi * 16 * 20 + ks) * 4u);
            #pragma unroll
            for (int pr = 0; pr < 2; pr++)
                ldsm4(bfr[pr], bAddr + (unsigned)(pr * 16 * 20 + ks) * 4u);
            #pragma unroll
            for (int mi = 0; mi < 4; mi++) {
                #pragma unroll
                for (int pr = 0; pr < 2; pr++) {
                    mma8(acc[mi][2 * pr],     af[mi], &bfr[pr][0]);
                    mma8(acc[mi][2 * pr + 1], af[mi], &bfr[pr][2]);
                }
            }
        }
        __syncthreads();
    }

    #pragma unroll
    for (int mi = 0; mi < 4; mi++) {
        const int r0 = m0 + wm + mi * 16 + qr;
        #pragma unroll
        for (int ni = 0; ni < 4; ni++) {
            const int c = e0 + wn + ni * 8 + qc * 2;
            float v0 = acc[mi][ni][0], v1 = acc[mi][ni][1];
            float v2 = acc[mi][ni][2], v3 = acc[mi][ni][3];
            if (CAUSAL) {
                v0 *= 0.03125f; v1 *= 0.03125f; v2 *= 0.03125f; v3 *= 0.03125f;
                if (c     > r0)     v0 = -INFINITY;
                if (c + 1 > r0)     v1 = -INFINITY;
                if (c     > r0 + 8) v2 = -INFINITY;
                if (c + 1 > r0 + 8) v3 = -INFINITY;
            }
            *(float2*)&C[(size_t)r0 * ldc + c]       = make_float2(v0, v1);
            *(float2*)&C[(size_t)(r0 + 8) * ldc + c] = make_float2(v2, v3);
        }
    }
}

// ---------------------------------------------------------------------------
// Row softmax over causal prefix; zero-fill to 128-tile boundary.
// ---------------------------------------------------------------------------
__global__ void __launch_bounds__(256) softmax_kernel()
{
    const int s = blockIdx.x;
    const int n = blockIdx.y;
    float* row = g_p + ((size_t)n * SEQ + s) * SEQ;
    const int len = s + 1;
    const int tile_end = ((s >> 7) + 1) << 7;
    const int tid = threadIdx.x;

    __shared__ float red[8];

    float m = -INFINITY;
    for (int t = tid; t < len; t += 256) m = fmaxf(m, row[t]);
    #pragma unroll
    for (int o = 16; o > 0; o >>= 1) m = fmaxf(m, __shfl_xor_sync(0xffffffffu, m, o));
    if ((tid & 31) == 0) red[tid >> 5] = m;
    __syncthreads();
    float bm = -INFINITY;
    #pragma unroll
    for (int w = 0; w < 8; w++) bm = fmaxf(bm, red[w]);
    __syncthreads();

    float ssum = 0.f;
    for (int t = tid; t < len; t += 256) {
        float e = __expf(row[t] - bm);
        row[t] = e;
        ssum += e;
    }
    #pragma unroll
    for (int o = 16; o > 0; o >>= 1) ssum += __shfl_xor_sync(0xffffffffu, ssum, o);
    if ((tid & 31) == 0) red[tid >> 5] = ssum;
    __syncthreads();
    float tot = 0.f;
    #pragma unroll
    for (int w = 0; w < 8; w++) tot += red[w];

    const float inv = 1.0f / tot;
    for (int t = tid; t < len; t += 256) row[t] *= inv;
    for (int t = len + tid; t < tile_end; t += 256) row[t] = 0.f;
}

// ---------------------------------------------------------------------------
// Y = P * V.  V tile stored n-major in smem (Bs[n][k]) so B fragments load
// via ldmatrix.  K-loop truncated at the diagonal 128-tile.
// ---------------------------------------------------------------------------
__global__ void __launch_bounds__(256) pv_tf32(float* __restrict__ Y)
{
    const int bj = blockIdx.x;   // e tile
    const int bi = blockIdx.y;   // s tile
    const int n  = blockIdx.z;
    const int s0 = bi * 128, e0 = bj * 128;

    __shared__ __align__(16) unsigned As[128][20];
    __shared__ __align__(16) unsigned Bs[128][20];   // [n][k]

    const float* P = g_p + (size_t)n * SEQ * SEQ + (size_t)s0 * SEQ;
    const float* V = g_v + (size_t)n * SEQ * DIM;

    const int tid  = threadIdx.x;
    const int lane = tid & 31, warp = tid >> 5;
    const int wm = (warp >> 2) * 64, wn = (warp & 3) * 32;
    const int qr = lane >> 2, qc = lane & 3;

    const int ar = tid >> 2,  ac = (tid & 3) * 4;   // A tile 128x16
    const int vn = tid & 127, vk0 = (tid >> 7) * 8; // V tile: 8 k's at column vn

    const int aRow = wm + (lane & 7) + ((lane >> 3) & 1) * 8;
    const int aCol = (lane >> 4) * 4;
    const unsigned aAddr = su32(&As[aRow][aCol]);
    const int bRow = wn + (lane & 7) + (lane >> 4) * 8;
    const int bCol = ((lane >> 3) & 1) * 4;
    const unsigned bAddr = su32(&Bs[bRow][bCol]);

    float acc[4][4][4] = {};

    const int ktiles = (bi + 1) * 8;
    float4 pa0 = *(const float4*)&P[(size_t)ar * SEQ + ac];
    float4 pa1 = *(const float4*)&P[(size_t)(ar + 64) * SEQ + ac];
    float pv[8];
    #pragma unroll
    for (int j = 0; j < 8; j++)
        pv[j] = V[(size_t)(vk0 + j) * DIM + e0 + vn];

    for (int kt = 0; kt < ktiles; kt++) {
        *(uint4*)&As[ar][ac]      = cvt4(pa0);
        *(uint4*)&As[ar + 64][ac] = cvt4(pa1);
        *(uint4*)&Bs[vn][vk0] =
            make_uint4(f2tf(pv[0]), f2tf(pv[1]), f2tf(pv[2]), f2tf(pv[3]));
        *(uint4*)&Bs[vn][vk0 + 4] =
            make_uint4(f2tf(pv[4]), f2tf(pv[5]), f2tf(pv[6]), f2tf(pv[7]));
        __syncthreads();

        if (kt + 1 < ktiles) {
            const int t0 = (kt + 1) * 16;
            pa0 = *(const float4*)&P[(size_t)ar * SEQ + t0 + ac];
            pa1 = *(const float4*)&P[(size_t)(ar + 64) * SEQ + t0 + ac];
            #pragma unroll
            for (int j = 0; j < 8; j++)
                pv[j] = V[(size_t)(t0 + vk0 + j) * DIM + e0 + vn];
        }

        #pragma unroll
        for (int ks = 0; ks < 16; ks += 8) {
            unsigned af[4][4], bfr[2][4];
            #pragma unroll
            for (int mi = 0; mi < 4; mi++)
                ldsm4(af[mi], aAddr + (unsigned)(mi * 16 * 20 + ks) * 4u);
            #pragma unroll
            for (int pr = 0; pr < 2; pr++)
                ldsm4(bfr[pr], bAddr + (unsigned)(pr * 16 * 20 + ks) * 4u);
            #pragma unroll
            for (int mi = 0; mi < 4; mi++) {
                #pragma unroll
                for (int pr = 0; pr < 2; pr++) {
                    mma8(acc[mi][2 * pr],     af[mi], &bfr[pr][0]);
                    mma8(acc[mi][2 * pr + 1], af[mi], &bfr[pr][2]);
                }
            }
        }
        __syncthreads();
    }

    #pragma unroll
    for (int mi = 0; mi < 4; mi++) {
        const int r0 = s0 + wm + mi * 16 + qr;
        #pragma unroll
        for (int ni = 0; ni < 4; ni++) {
            const int c = e0 + wn + ni * 8 + qc * 2;
            *(float2*)&Y[((size_t)n * SEQ + r0) * DIM + c] =
                make_float2(acc[mi][ni][0], acc[mi][ni][1]);
            *(float2*)&Y[((size_t)n * SEQ + r0 + 8) * DIM + c] =
                make_float2(acc[mi][ni][2], acc[mi][ni][3]);
        }
    }
}

// ---------------------------------------------------------------------------
// Launch.
// ---------------------------------------------------------------------------
extern "C" void kernel_launch(void* const* d_in, const int* in_sizes, int n_in,
                              void* d_out, int out_size)
{
    (void)in_sizes; (void)n_in; (void)out_size;
    const float* query = (const float*)d_in[0];
    const float* key   = (const float*)d_in[1];
    const float* value = (const float*)d_in[2];
    const float* Wq    = (const float*)d_in[4];
    const float* Wk    = (const float*)d_in[5];
    const float* Wv    = (const float*)d_in[6];
    float* out = (float*)d_out;

    float *q_ptr, *k_ptr, *v_ptr, *p_ptr;
    cudaGetSymbolAddress((void**)&q_ptr, g_q);
    cudaGetSymbolAddress((void**)&k_ptr, g_k);
    cudaGetSymbolAddress((void**)&v_ptr, g_v);
    cudaGetSymbolAddress((void**)&p_ptr, g_p);

    dim3 pg(DIM / 128, (NB * SEQ) / 128, 1);
    gemm_tn<false><<<pg, 256>>>(query, Wq, q_ptr, 0, 0, 0, DIM);
    gemm_tn<false><<<pg, 256>>>(key,   Wk, k_ptr, 0, 0, 0, DIM);
    gemm_tn<false><<<pg, 256>>>(value, Wv, v_ptr, 0, 0, 0, DIM);

    dim3 sg(SEQ / 128, SEQ / 128, NB);
    gemm_tn<true><<<sg, 256>>>(q_ptr, k_ptr, p_ptr,
                               (size_t)SEQ * DIM, (size_t)SEQ * DIM,
                               (size_t)SEQ * SEQ, SEQ);

    dim3 smg(SEQ, NB);
    softmax_kernel<<<smg, 256>>>();

    dim3 vg(DIM / 128, SEQ / 128, NB);
    pv_tf32<<<vg, 256>>>(out);
}

// round 5
// speedup vs baseline: 3.7137x; 1.2971x over previous
#include <cuda_runtime.h>
#include <math.h>

#define NB   4
#define SEQ  2048
#define DIM  1024

__device__ float g_q[(size_t)NB * SEQ * DIM];
__device__ float g_k[(size_t)NB * SEQ * DIM];
__device__ float g_v[(size_t)NB * SEQ * DIM];
__device__ float g_p[(size_t)NB * SEQ * SEQ];

// ---------------------------------------------------------------------------
// Helpers
// ---------------------------------------------------------------------------
__device__ __forceinline__ unsigned f2tf(float f) {
    unsigned u;
    asm("cvt.rna.tf32.f32 %0, %1;" : "=r"(u) : "f"(f));
    return u;
}
__device__ __forceinline__ void mma8(float* c, const unsigned* a, const unsigned* b) {
    asm volatile(
        "mma.sync.aligned.m16n8k8.row.col.f32.tf32.tf32.f32 "
        "{%0,%1,%2,%3}, {%4,%5,%6,%7}, {%8,%9}, {%0,%1,%2,%3};"
        : "+f"(c[0]), "+f"(c[1]), "+f"(c[2]), "+f"(c[3])
        : "r"(a[0]), "r"(a[1]), "r"(a[2]), "r"(a[3]), "r"(b[0]), "r"(b[1]));
}
__device__ __forceinline__ unsigned su32(const void* p) {
    return (unsigned)__cvta_generic_to_shared(p);
}
__device__ __forceinline__ void ldsm4(unsigned* r, unsigned addr) {
    asm volatile("ldmatrix.sync.aligned.m8n8.x4.shared.b16 {%0,%1,%2,%3}, [%4];"
                 : "=r"(r[0]), "=r"(r[1]), "=r"(r[2]), "=r"(r[3]) : "r"(addr));
}
__device__ __forceinline__ void cpa16(unsigned dst, const float* src) {
    asm volatile("cp.async.cg.shared.global [%0], [%1], 16;" :: "r"(dst), "l"(src));
}
__device__ __forceinline__ void cp_commit() {
    asm volatile("cp.async.commit_group;");
}
__device__ __forceinline__ void cp_wait1() {
    asm volatile("cp.async.wait_group 1;");
}

#define STAGE_BYTES 10240u   // 128*20*4

struct __align__(16) SmAB { float A[2][128][20]; float B[2][128][20]; };

// ---------------------------------------------------------------------------
// Core: C = A * B^T (both K-major).  128x128 tile, BK=16, double-buffered
// cp.async, raw fp32 in smem, cvt.rna on fragments, tf32 mma.
// ---------------------------------------------------------------------------
template<bool CAUSAL>
__device__ __forceinline__ void gemm_core(SmAB* sm,
                                          const float* __restrict__ A,
                                          const float* __restrict__ B,
                                          float* __restrict__ C,
                                          int m0, int e0, int ldc, int NK)
{
    const int tid  = threadIdx.x;
    const int lane = tid & 31, warp = tid >> 5;
    const int wm = (warp >> 2) * 64, wn = (warp & 3) * 32;
    const int qr = lane >> 2, qc = lane & 3;
    const int r0 = tid >> 2, c0 = (tid & 3) * 4;

    const int aRow = wm + (lane & 7) + ((lane >> 3) & 1) * 8;
    const int aCol = (lane >> 4) * 4;
    const unsigned aAddr = su32(&sm->A[0][aRow][aCol]);
    const int bRow = wn + (lane & 7) + (lane >> 4) * 8;
    const int bCol = ((lane >> 3) & 1) * 4;
    const unsigned bAddr = su32(&sm->B[0][bRow][bCol]);

    const unsigned stA0 = su32(&sm->A[0][r0][c0]);
    const unsigned stA1 = su32(&sm->A[0][r0 + 64][c0]);
    const unsigned stB0 = su32(&sm->B[0][r0][c0]);
    const unsigned stB1 = su32(&sm->B[0][r0 + 64][c0]);

    float acc[4][4][4] = {};

    #define LOAD_STAGE(st, k0)                                                   \
        do {                                                                     \
            cpa16(stA0 + (st) * STAGE_BYTES, A + (size_t)r0 * DIM + (k0) + c0);  \
            cpa16(stA1 + (st) * STAGE_BYTES, A + (size_t)(r0 + 64) * DIM + (k0) + c0); \
            cpa16(stB0 + (st) * STAGE_BYTES, B + (size_t)r0 * DIM + (k0) + c0);  \
            cpa16(stB1 + (st) * STAGE_BYTES, B + (size_t)(r0 + 64) * DIM + (k0) + c0); \
            cp_commit();                                                         \
        } while (0)

    LOAD_STAGE(0, 0);
    LOAD_STAGE(1, 16);
    cp_wait1();
    __syncthreads();

    for (int kt = 0; kt < NK; kt++) {
        const int st = kt & 1;
        const unsigned aOff = aAddr + st * STAGE_BYTES;
        const unsigned bOff = bAddr + st * STAGE_BYTES;

        #pragma unroll
        for (int ks = 0; ks < 16; ks += 8) {
            unsigned af[4][4], bfr[2][4];
            #pragma unroll
            for (int mi = 0; mi < 4; mi++)
                ldsm4(af[mi], aOff + (unsigned)(mi * 16 * 20 + ks) * 4u);
            #pragma unroll
            for (int pr = 0; pr < 2; pr++)
                ldsm4(bfr[pr], bOff + (unsigned)(pr * 16 * 20 + ks) * 4u);
            #pragma unroll
            for (int mi = 0; mi < 4; mi++)
                #pragma unroll
                for (int j = 0; j < 4; j++)
                    af[mi][j] = f2tf(__uint_as_float(af[mi][j]));
            #pragma unroll
            for (int pr = 0; pr < 2; pr++)
                #pragma unroll
                for (int j = 0; j < 4; j++)
                    bfr[pr][j] = f2tf(__uint_as_float(bfr[pr][j]));
            #pragma unroll
            for (int mi = 0; mi < 4; mi++) {
                #pragma unroll
                for (int pr = 0; pr < 2; pr++) {
                    mma8(acc[mi][2 * pr],     af[mi], &bfr[pr][0]);
                    mma8(acc[mi][2 * pr + 1], af[mi], &bfr[pr][2]);
                }
            }
        }
        __syncthreads();
        if (kt + 2 < NK) LOAD_STAGE(st, (kt + 2) * 16);
        else             cp_commit();
        cp_wait1();
        __syncthreads();
    }
    #undef LOAD_STAGE

    #pragma unroll
    for (int mi = 0; mi < 4; mi++) {
        const int rr = m0 + wm + mi * 16 + qr;
        #pragma unroll
        for (int ni = 0; ni < 4; ni++) {
            const int c = e0 + wn + ni * 8 + qc * 2;
            float v0 = acc[mi][ni][0], v1 = acc[mi][ni][1];
            float v2 = acc[mi][ni][2], v3 = acc[mi][ni][3];
            if (CAUSAL) {
                v0 *= 0.03125f; v1 *= 0.03125f; v2 *= 0.03125f; v3 *= 0.03125f;
                if (c     > rr)     v0 = -INFINITY;
                if (c + 1 > rr)     v1 = -INFINITY;
                if (c     > rr + 8) v2 = -INFINITY;
                if (c + 1 > rr + 8) v3 = -INFINITY;
            }
            *(float2*)&C[(size_t)rr * ldc + c]       = make_float2(v0, v1);
            *(float2*)&C[(size_t)(rr + 8) * ldc + c] = make_float2(v2, v3);
        }
    }
}

// ---------------------------------------------------------------------------
// Projections: one launch, z selects (X, W, Y).
// ---------------------------------------------------------------------------
__global__ void __launch_bounds__(256, 2)
proj3_kernel(const float* __restrict__ q, const float* __restrict__ k,
             const float* __restrict__ v,
             const float* __restrict__ Wq, const float* __restrict__ Wk,
             const float* __restrict__ Wv,
             float* __restrict__ yq, float* __restrict__ yk, float* __restrict__ yv)
{
    __shared__ SmAB sm;
    const int z = blockIdx.z;
    const float* X = (z == 0) ? q : (z == 1) ? k : v;
    const float* W = (z == 0) ? Wq : (z == 1) ? Wk : Wv;
    float*       Y = (z == 0) ? yq : (z == 1) ? yk : yv;
    const int bi = blockIdx.y, bj = blockIdx.x;
    gemm_core<false>(&sm,
                     X + (size_t)bi * 128 * DIM,
                     W + (size_t)bj * 128 * DIM,
                     Y, bi * 128, bj * 128, DIM, DIM / 16);
}

// ---------------------------------------------------------------------------
// Scores (causal): tile-skip + scale/mask epilogue.
// ---------------------------------------------------------------------------
__global__ void __launch_bounds__(256, 2) scores_mma_kernel()
{
    const int bj = blockIdx.x, bi = blockIdx.y, n = blockIdx.z;
    if (bj > bi) return;
    __shared__ SmAB sm;
    gemm_core<true>(&sm,
                    g_q + ((size_t)n * SEQ + (size_t)bi * 128) * DIM,
                    g_k + ((size_t)n * SEQ + (size_t)bj * 128) * DIM,
                    g_p + (size_t)n * SEQ * SEQ,
                    bi * 128, bj * 128, SEQ, DIM / 16);
}

// ---------------------------------------------------------------------------
// Row softmax over causal prefix; zero-fill to 128-tile boundary.
// ---------------------------------------------------------------------------
__global__ void __launch_bounds__(256) softmax_kernel()
{
    const int s = blockIdx.x;
    const int n = blockIdx.y;
    float* row = g_p + ((size_t)n * SEQ + s) * SEQ;
    const int len = s + 1;
    const int tile_end = ((s >> 7) + 1) << 7;
    const int tid = threadIdx.x;

    __shared__ float red[8];

    float m = -INFINITY;
    for (int t = tid; t < len; t += 256) m = fmaxf(m, row[t]);
    #pragma unroll
    for (int o = 16; o > 0; o >>= 1) m = fmaxf(m, __shfl_xor_sync(0xffffffffu, m, o));
    if ((tid & 31) == 0) red[tid >> 5] = m;
    __syncthreads();
    float bm = -INFINITY;
    #pragma unroll
    for (int w = 0; w < 8; w++) bm = fmaxf(bm, red[w]);
    __syncthreads();

    float ssum = 0.f;
    for (int t = tid; t < len; t += 256) {
        float e = __expf(row[t] - bm);
        row[t] = e;
        ssum += e;
    }
    #pragma unroll
    for (int o = 16; o > 0; o >>= 1) ssum += __shfl_xor_sync(0xffffffffu, ssum, o);
    if ((tid & 31) == 0) red[tid >> 5] = ssum;
    __syncthreads();
    float tot = 0.f;
    #pragma unroll
    for (int w = 0; w < 8; w++) tot += red[w];

    const float inv = 1.0f / tot;
    for (int t = tid; t < len; t += 256) row[t] *= inv;
    for (int t = len + tid; t < tile_end; t += 256) row[t] = 0.f;
}

// ---------------------------------------------------------------------------
// PV: Y = P * V.  A (P) K-major tiles; V staged k-major [16][136] (stride
// 136 % 32 == 8 -> conflict-free B-fragment LDS).  K-loop stops at diagonal.
// ---------------------------------------------------------------------------
struct __align__(16) SmPV { float A[2][128][20]; float V[2][16][136]; };
#define VSTAGE_BYTES (16u * 136u * 4u)

__global__ void __launch_bounds__(256, 2) pv_mma_kernel(float* __restrict__ Y)
{
    const int bj = blockIdx.x;   // e tile
    const int bi = blockIdx.y;   // s tile
    const int n  = blockIdx.z;
    const int s0 = bi * 128, e0 = bj * 128;

    __shared__ SmPV sm;

    const float* P = g_p + (size_t)n * SEQ * SEQ + (size_t)s0 * SEQ;
    const float* V = g_v + (size_t)n * SEQ * DIM;

    const int tid  = threadIdx.x;
    const int lane = tid & 31, warp = tid >> 5;
    const int wm = (warp >> 2) * 64, wn = (warp & 3) * 32;
    const int qr = lane >> 2, qc = lane & 3;
    const int r0 = tid >> 2, c0 = (tid & 3) * 4;
    const int vr = tid >> 5, vc = (tid & 31) * 4;

    const int aRow = wm + (lane & 7) + ((lane >> 3) & 1) * 8;
    const int aCol = (lane >> 4) * 4;
    const unsigned aAddr = su32(&sm.A[0][aRow][aCol]);

    const unsigned stA0 = su32(&sm.A[0][r0][c0]);
    const unsigned stA1 = su32(&sm.A[0][r0 + 64][c0]);
    const unsigned stV0 = su32(&sm.V[0][vr][vc]);
    const unsigned stV1 = su32(&sm.V[0][vr + 8][vc]);

    float acc[4][4][4] = {};

    #define LOAD_STAGE_PV(st, t0)                                                  \
        do {                                                                       \
            cpa16(stA0 + (st) * STAGE_BYTES, P + (size_t)r0 * SEQ + (t0) + c0);    \
            cpa16(stA1 + (st) * STAGE_BYTES, P + (size_t)(r0 + 64) * SEQ + (t0) + c0); \
            cpa16(stV0 + (st) * VSTAGE_BYTES, V + (size_t)((t0) + vr) * DIM + e0 + vc); \
            cpa16(stV1 + (st) * VSTAGE_BYTES, V + (size_t)((t0) + vr + 8) * DIM + e0 + vc); \
            cp_commit();                                                           \
        } while (0)

    const int ktiles = (bi + 1) * 8;
    LOAD_STAGE_PV(0, 0);
    LOAD_STAGE_PV(1, 16);
    cp_wait1();
    __syncthreads();

    for (int kt = 0; kt < ktiles; kt++) {
        const int st = kt & 1;
        const unsigned aOff = aAddr + st * STAGE_BYTES;

        #pragma unroll
        for (int ks = 0; ks < 16; ks += 8) {
            unsigned af[4][4], bfr[4][2];
            #pragma unroll
            for (int mi = 0; mi < 4; mi++)
                ldsm4(af[mi], aOff + (unsigned)(mi * 16 * 20 + ks) * 4u);
            #pragma unroll
            for (int mi = 0; mi < 4; mi++)
                #pragma unroll
                for (int j = 0; j < 4; j++)
                    af[mi][j] = f2tf(__uint_as_float(af[mi][j]));
            #pragma unroll
            for (int ni = 0; ni < 4; ni++) {
                const int cc = wn + ni * 8 + qr;
                bfr[ni][0] = f2tf(sm.V[st][ks + qc][cc]);
                bfr[ni][1] = f2tf(sm.V[st][ks + qc + 4][cc]);
            }
            #pragma unroll
            for (int mi = 0; mi < 4; mi++)
                #pragma unroll
                for (int ni = 0; ni < 4; ni++)
                    mma8(acc[mi][ni], af[mi], bfr[ni]);
        }
        __syncthreads();
        if (kt + 2 < ktiles) LOAD_STAGE_PV(st, (kt + 2) * 16);
        else                 cp_commit();
        cp_wait1();
        __syncthreads();
    }
    #undef LOAD_STAGE_PV

    #pragma unroll
    for (int mi = 0; mi < 4; mi++) {
        const int rr = s0 + wm + mi * 16 + qr;
        #pragma unroll
        for (int ni = 0; ni < 4; ni++) {
            const int c = e0 + wn + ni * 8 + qc * 2;
            *(float2*)&Y[((size_t)n * SEQ + rr) * DIM + c] =
                make_float2(acc[mi][ni][0], acc[mi][ni][1]);
            *(float2*)&Y[((size_t)n * SEQ + rr + 8) * DIM + c] =
                make_float2(acc[mi][ni][2], acc[mi][ni][3]);
        }
    }
}

// ---------------------------------------------------------------------------
// Launch.
// ---------------------------------------------------------------------------
extern "C" void kernel_launch(void* const* d_in, const int* in_sizes, int n_in,
                              void* d_out, int out_size)
{
    (void)in_sizes; (void)n_in; (void)out_size;
    const float* query = (const float*)d_in[0];
    const float* key   = (const float*)d_in[1];
    const float* value = (const float*)d_in[2];
    const float* Wq    = (const float*)d_in[4];
    const float* Wk    = (const float*)d_in[5];
    const float* Wv    = (const float*)d_in[6];
    float* out = (float*)d_out;

    float *q_ptr, *k_ptr, *v_ptr;
    cudaGetSymbolAddress((void**)&q_ptr, g_q);
    cudaGetSymbolAddress((void**)&k_ptr, g_k);
    cudaGetSymbolAddress((void**)&v_ptr, g_v);

    dim3 pg(DIM / 128, (NB * SEQ) / 128, 3);
    proj3_kernel<<<pg, 256>>>(query, key, value, Wq, Wk, Wv, q_ptr, k_ptr, v_ptr);

    dim3 sg(SEQ / 128, SEQ / 128, NB);
    scores_mma_kernel<<<sg, 256>>>();

    dim3 smg(SEQ, NB);
    softmax_kernel<<<smg, 256>>>();

    dim3 vg(DIM / 128, SEQ / 128, NB);
    pv_mma_kernel<<<vg, 256>>>(out);
}

// round 6
// speedup vs baseline: 3.7364x; 1.0061x over previous
#include <cuda_runtime.h>
#include <math.h>

#define NB   4
#define SEQ  2048
#define DIM  1024

__device__ float g_q[(size_t)NB * SEQ * DIM];
__device__ float g_k[(size_t)NB * SEQ * DIM];
__device__ float g_v[(size_t)NB * SEQ * DIM];
__device__ float g_p[(size_t)NB * SEQ * SEQ];

// ---------------------------------------------------------------------------
// Helpers
// ---------------------------------------------------------------------------
__device__ __forceinline__ unsigned f2tf(float f) {
    unsigned u;
    asm("cvt.rna.tf32.f32 %0, %1;" : "=r"(u) : "f"(f));
    return u;
}
__device__ __forceinline__ void mma8(float* c, const unsigned* a, const unsigned* b) {
    asm volatile(
        "mma.sync.aligned.m16n8k8.row.col.f32.tf32.tf32.f32 "
        "{%0,%1,%2,%3}, {%4,%5,%6,%7}, {%8,%9}, {%0,%1,%2,%3};"
        : "+f"(c[0]), "+f"(c[1]), "+f"(c[2]), "+f"(c[3])
        : "r"(a[0]), "r"(a[1]), "r"(a[2]), "r"(a[3]), "r"(b[0]), "r"(b[1]));
}
__device__ __forceinline__ unsigned su32(const void* p) {
    return (unsigned)__cvta_generic_to_shared(p);
}
__device__ __forceinline__ void ldsm4(unsigned* r, unsigned addr) {
    asm volatile("ldmatrix.sync.aligned.m8n8.x4.shared.b16 {%0,%1,%2,%3}, [%4];"
                 : "=r"(r[0]), "=r"(r[1]), "=r"(r[2]), "=r"(r[3]) : "r"(addr));
}
__device__ __forceinline__ void cpa16(unsigned dst, const float* src) {
    asm volatile("cp.async.cg.shared.global [%0], [%1], 16;" :: "r"(dst), "l"(src));
}
__device__ __forceinline__ void cp_commit() {
    asm volatile("cp.async.commit_group;");
}
__device__ __forceinline__ void cp_wait1() {
    asm volatile("cp.async.wait_group 1;");
}

#define STAGE_BYTES 10240u        // 128*20*4
#define AB_SMEM     (6u * STAGE_BYTES)          // 61440
#define VSTAGE_BYTES (16u * 136u * 4u)          // 8704
#define PV_SMEM     (3u * STAGE_BYTES + 3u * VSTAGE_BYTES)  // 56832

// ---------------------------------------------------------------------------
// Core: C = A * B^T (both K-major).  128x128 tile, BK=16, 3-stage cp.async
// pipeline, ONE __syncthreads per k-tile.  CVT: convert fragments to tf32
// (needed when inputs are raw fp32).  TFOUT: store tf32-rounded bits.
// ---------------------------------------------------------------------------
template<bool CAUSAL, bool CVT, bool TFOUT>
__device__ __forceinline__ void gemm_core(char* smem,
                                          const float* __restrict__ A,
                                          const float* __restrict__ B,
                                          float* __restrict__ C,
                                          int m0, int e0, int ldc, int NK)
{
    float (*As)[128][20] = (float(*)[128][20])smem;
    float (*Bs)[128][20] = (float(*)[128][20])(smem + 3u * STAGE_BYTES);

    const int tid  = threadIdx.x;
    const int lane = tid & 31, warp = tid >> 5;
    const int wm = (warp >> 2) * 64, wn = (warp & 3) * 32;
    const int qr = lane >> 2, qc = lane & 3;
    const int r0 = tid >> 2, c0 = (tid & 3) * 4;

    const int aRow = wm + (lane & 7) + ((lane >> 3) & 1) * 8;
    const int aCol = (lane >> 4) * 4;
    const unsigned aAddr = su32(&As[0][aRow][aCol]);
    const int bRow = wn + (lane & 7) + (lane >> 4) * 8;
    const int bCol = ((lane >> 3) & 1) * 4;
    const unsigned bAddr = su32(&Bs[0][bRow][bCol]);

    const unsigned stA0 = su32(&As[0][r0][c0]);
    const unsigned stA1 = su32(&As[0][r0 + 64][c0]);
    const unsigned stB0 = su32(&Bs[0][r0][c0]);
    const unsigned stB1 = su32(&Bs[0][r0 + 64][c0]);

    float acc[4][4][4] = {};

    #define LOADG(st, k0)                                                        \
        do {                                                                     \
            cpa16(stA0 + (st) * STAGE_BYTES, A + (size_t)r0 * DIM + (k0) + c0);  \
            cpa16(stA1 + (st) * STAGE_BYTES, A + (size_t)(r0 + 64) * DIM + (k0) + c0); \
            cpa16(stB0 + (st) * STAGE_BYTES, B + (size_t)r0 * DIM + (k0) + c0);  \
            cpa16(stB1 + (st) * STAGE_BYTES, B + (size_t)(r0 + 64) * DIM + (k0) + c0); \
            cp_commit();                                                         \
        } while (0)

    LOADG(0, 0);
    LOADG(1, 16);

    for (int kt = 0; kt < NK; kt++) {
        const int st = kt % 3;
        cp_wait1();
        __syncthreads();
        if (kt + 2 < NK) {
            const int nst = (kt + 2) % 3;
            LOADG(nst, (kt + 2) * 16);
        }
        const unsigned aOff = aAddr + st * STAGE_BYTES;
        const unsigned bOff = bAddr + st * STAGE_BYTES;

        #pragma unroll
        for (int ks = 0; ks < 16; ks += 8) {
            unsigned af[4][4], bfr[2][4];
            #pragma unroll
            for (int mi = 0; mi < 4; mi++)
                ldsm4(af[mi], aOff + (unsigned)(mi * 16 * 20 + ks) * 4u);
            #pragma unroll
            for (int pr = 0; pr < 2; pr++)
                ldsm4(bfr[pr], bOff + (unsigned)(pr * 16 * 20 + ks) * 4u);
            if (CVT) {
                #pragma unroll
                for (int mi = 0; mi < 4; mi++)
                    #pragma unroll
                    for (int j = 0; j < 4; j++)
                        af[mi][j] = f2tf(__uint_as_float(af[mi][j]));
                #pragma unroll
                for (int pr = 0; pr < 2; pr++)
                    #pragma unroll
                    for (int j = 0; j < 4; j++)
                        bfr[pr][j] = f2tf(__uint_as_float(bfr[pr][j]));
            }
            #pragma unroll
            for (int mi = 0; mi < 4; mi++) {
                #pragma unroll
                for (int pr = 0; pr < 2; pr++) {
                    mma8(acc[mi][2 * pr],     af[mi], &bfr[pr][0]);
                    mma8(acc[mi][2 * pr + 1], af[mi], &bfr[pr][2]);
                }
            }
        }
    }
    #undef LOADG

    #pragma unroll
    for (int mi = 0; mi < 4; mi++) {
        const int rr = m0 + wm + mi * 16 + qr;
        #pragma unroll
        for (int ni = 0; ni < 4; ni++) {
            const int c = e0 + wn + ni * 8 + qc * 2;
            float v0 = acc[mi][ni][0], v1 = acc[mi][ni][1];
            float v2 = acc[mi][ni][2], v3 = acc[mi][ni][3];
            if (CAUSAL) {
                v0 *= 0.03125f; v1 *= 0.03125f; v2 *= 0.03125f; v3 *= 0.03125f;
                if (c     > rr)     v0 = -INFINITY;
                if (c + 1 > rr)     v1 = -INFINITY;
                if (c     > rr + 8) v2 = -INFINITY;
                if (c + 1 > rr + 8) v3 = -INFINITY;
            }
            if (TFOUT) {
                v0 = __uint_as_float(f2tf(v0));
                v1 = __uint_as_float(f2tf(v1));
                v2 = __uint_as_float(f2tf(v2));
                v3 = __uint_as_float(f2tf(v3));
            }
            *(float2*)&C[(size_t)rr * ldc + c]       = make_float2(v0, v1);
            *(float2*)&C[(size_t)(rr + 8) * ldc + c] = make_float2(v2, v3);
        }
    }
}

// ---------------------------------------------------------------------------
// Projections: one launch, z selects (X, W, Y).  Stores tf32-rounded bits.
// ---------------------------------------------------------------------------
__global__ void __launch_bounds__(256, 2)
proj3_kernel(const float* __restrict__ q, const float* __restrict__ k,
             const float* __restrict__ v,
             const float* __restrict__ Wq, const float* __restrict__ Wk,
             const float* __restrict__ Wv,
             float* __restrict__ yq, float* __restrict__ yk, float* __restrict__ yv)
{
    extern __shared__ char smem[];
    const int z = blockIdx.z;
    const float* X = (z == 0) ? q : (z == 1) ? k : v;
    const float* W = (z == 0) ? Wq : (z == 1) ? Wk : Wv;
    float*       Y = (z == 0) ? yq : (z == 1) ? yk : yv;
    const int bi = blockIdx.y, bj = blockIdx.x;
    gemm_core<false, true, true>(smem,
                                 X + (size_t)bi * 128 * DIM,
                                 W + (size_t)bj * 128 * DIM,
                                 Y, bi * 128, bj * 128, DIM, DIM / 16);
}

// ---------------------------------------------------------------------------
// Scores (causal): operands already tf32 bits -> no cvt in inner loop.
// ---------------------------------------------------------------------------
__global__ void __launch_bounds__(256, 2) scores_mma_kernel()
{
    const int bj = blockIdx.x, bi = blockIdx.y, n = blockIdx.z;
    if (bj > bi) return;
    extern __shared__ char smem[];
    gemm_core<true, false, false>(smem,
                                  g_q + ((size_t)n * SEQ + (size_t)bi * 128) * DIM,
                                  g_k + ((size_t)n * SEQ + (size_t)bj * 128) * DIM,
                                  g_p + (size_t)n * SEQ * SEQ,
                                  bi * 128, bj * 128, SEQ, DIM / 16);
}

// ---------------------------------------------------------------------------
// Row softmax over causal prefix; stores tf32-rounded probabilities and
// zero-fills to the 128-tile boundary.
// ---------------------------------------------------------------------------
__global__ void __launch_bounds__(256) softmax_kernel()
{
    const int s = blockIdx.x;
    const int n = blockIdx.y;
    float* row = g_p + ((size_t)n * SEQ + s) * SEQ;
    const int len = s + 1;
    const int tile_end = ((s >> 7) + 1) << 7;
    const int tid = threadIdx.x;

    __shared__ float red[8];

    float m = -INFINITY;
    for (int t = tid; t < len; t += 256) m = fmaxf(m, row[t]);
    #pragma unroll
    for (int o = 16; o > 0; o >>= 1) m = fmaxf(m, __shfl_xor_sync(0xffffffffu, m, o));
    if ((tid & 31) == 0) red[tid >> 5] = m;
    __syncthreads();
    float bm = -INFINITY;
    #pragma unroll
    for (int w = 0; w < 8; w++) bm = fmaxf(bm, red[w]);
    __syncthreads();

    float ssum = 0.f;
    for (int t = tid; t < len; t += 256) {
        float e = __expf(row[t] - bm);
        row[t] = e;
        ssum += e;
    }
    #pragma unroll
    for (int o = 16; o > 0; o >>= 1) ssum += __shfl_xor_sync(0xffffffffu, ssum, o);
    if ((tid & 31) == 0) red[tid >> 5] = ssum;
    __syncthreads();
    float tot = 0.f;
    #pragma unroll
    for (int w = 0; w < 8; w++) tot += red[w];

    const float inv = 1.0f / tot;
    for (int t = tid; t < len; t += 256)
        row[t] = __uint_as_float(f2tf(row[t] * inv));
    for (int t = len + tid; t < tile_end; t += 256) row[t] = 0.f;
}

// ---------------------------------------------------------------------------
// PV: Y = P * V.  Both operands already tf32 bits.  3-stage pipeline,
// V staged k-major [16][136] (136%32==8 -> conflict-free scalar B loads).
// ---------------------------------------------------------------------------
__global__ void __launch_bounds__(256, 2) pv_mma_kernel(float* __restrict__ Y)
{
    const int bj = blockIdx.x;   // e tile
    const int bi = blockIdx.y;   // s tile
    const int n  = blockIdx.z;
    const int s0 = bi * 128, e0 = bj * 128;

    extern __shared__ char smem[];
    float (*As)[128][20] = (float(*)[128][20])smem;
    float (*Vs)[16][136] = (float(*)[16][136])(smem + 3u * STAGE_BYTES);

    const float* P = g_p + (size_t)n * SEQ * SEQ + (size_t)s0 * SEQ;
    const float* V = g_v + (size_t)n * SEQ * DIM;

    const int tid  = threadIdx.x;
    const int lane = tid & 31, warp = tid >> 5;
    const int wm = (warp >> 2) * 64, wn = (warp & 3) * 32;
    const int qr = lane >> 2, qc = lane & 3;
    const int r0 = tid >> 2, c0 = (tid & 3) * 4;
    const int vr = tid >> 5, vc = (tid & 31) * 4;

    const int aRow = wm + (lane & 7) + ((lane >> 3) & 1) * 8;
    const int aCol = (lane >> 4) * 4;
    const unsigned aAddr = su32(&As[0][aRow][aCol]);

    const unsigned stA0 = su32(&As[0][r0][c0]);
    const unsigned stA1 = su32(&As[0][r0 + 64][c0]);
    const unsigned stV0 = su32(&Vs[0][vr][vc]);
    const unsigned stV1 = su32(&Vs[0][vr + 8][vc]);

    float acc[4][4][4] = {};

    #define LOADPV(st, t0)                                                         \
        do {                                                                       \
            cpa16(stA0 + (st) * STAGE_BYTES, P + (size_t)r0 * SEQ + (t0) + c0);    \
            cpa16(stA1 + (st) * STAGE_BYTES, P + (size_t)(r0 + 64) * SEQ + (t0) + c0); \
            cpa16(stV0 + (st) * VSTAGE_BYTES, V + (size_t)((t0) + vr) * DIM + e0 + vc); \
            cpa16(stV1 + (st) * VSTAGE_BYTES, V + (size_t)((t0) + vr + 8) * DIM + e0 + vc); \
            cp_commit();                                                           \
        } while (0)

    const int ktiles = (bi + 1) * 8;
    LOADPV(0, 0);
    LOADPV(1, 16);

    for (int kt = 0; kt < ktiles; kt++) {
        const int st = kt % 3;
        cp_wait1();
        __syncthreads();
        if (kt + 2 < ktiles) {
            const int nst = (kt + 2) % 3;
            LOADPV(nst, (kt + 2) * 16);
        }
        const unsigned aOff = aAddr + st * STAGE_BYTES;

        #pragma unroll
        for (int ks = 0; ks < 16; ks += 8) {
            unsigned af[4][4], bfr[4][2];
            #pragma unroll
            for (int mi = 0; mi < 4; mi++)
                ldsm4(af[mi], aOff + (unsigned)(mi * 16 * 20 + ks) * 4u);
            #pragma unroll
            for (int ni = 0; ni < 4; ni++) {
                const int cc = wn + ni * 8 + qr;
                bfr[ni][0] = __float_as_uint(Vs[st][ks + qc][cc]);
                bfr[ni][1] = __float_as_uint(Vs[st][ks + qc + 4][cc]);
            }
            #pragma unroll
            for (int mi = 0; mi < 4; mi++)
                #pragma unroll
                for (int ni = 0; ni < 4; ni++)
                    mma8(acc[mi][ni], af[mi], bfr[ni]);
        }
    }
    #undef LOADPV

    #pragma unroll
    for (int mi = 0; mi < 4; mi++) {
        const int rr = s0 + wm + mi * 16 + qr;
        #pragma unroll
        for (int ni = 0; ni < 4; ni++) {
            const int c = e0 + wn + ni * 8 + qc * 2;
            *(float2*)&Y[((size_t)n * SEQ + rr) * DIM + c] =
                make_float2(acc[mi][ni][0], acc[mi][ni][1]);
            *(float2*)&Y[((size_t)n * SEQ + rr + 8) * DIM + c] =
                make_float2(acc[mi][ni][2], acc[mi][ni][3]);
        }
    }
}

// ---------------------------------------------------------------------------
// Launch.
// ---------------------------------------------------------------------------
extern "C" void kernel_launch(void* const* d_in, const int* in_sizes, int n_in,
                              void* d_out, int out_size)
{
    (void)in_sizes; (void)n_in; (void)out_size;
    const float* query = (const float*)d_in[0];
    const float* key   = (const float*)d_in[1];
    const float* value = (const float*)d_in[2];
    const float* Wq    = (const float*)d_in[4];
    const float* Wk    = (const float*)d_in[5];
    const float* Wv    = (const float*)d_in[6];
    float* out = (float*)d_out;

    float *q_ptr, *k_ptr, *v_ptr;
    cudaGetSymbolAddress((void**)&q_ptr, g_q);
    cudaGetSymbolAddress((void**)&k_ptr, g_k);
    cudaGetSymbolAddress((void**)&v_ptr, g_v);

    cudaFuncSetAttribute(proj3_kernel,
                         cudaFuncAttributeMaxDynamicSharedMemorySize, AB_SMEM);
    cudaFuncSetAttribute(scores_mma_kernel,
                         cudaFuncAttributeMaxDynamicSharedMemorySize, AB_SMEM);
    cudaFuncSetAttribute(pv_mma_kernel,
                         cudaFuncAttributeMaxDynamicSharedMemorySize, PV_SMEM);

    dim3 pg(DIM / 128, (NB * SEQ) / 128, 3);
    proj3_kernel<<<pg, 256, AB_SMEM>>>(query, key, value, Wq, Wk, Wv,
                                       q_ptr, k_ptr, v_ptr);

    dim3 sg(SEQ / 128, SEQ / 128, NB);
    scores_mma_kernel<<<sg, 256, AB_SMEM>>>();

    dim3 smg(SEQ, NB);
    softmax_kernel<<<smg, 256>>>();

    dim3 vg(DIM / 128, SEQ / 128, NB);
    pv_mma_kernel<<<vg, 256, PV_SMEM>>>(out);
}